// round 3
// baseline (speedup 1.0000x reference)
#include <cuda_runtime.h>
#include <cuda_bf16.h>

#define BB   64
#define LL   4096
#define DD   256
#define VV   33
#define NT   1024
#define GRID 128
#define NW   (NT / 32)

// Persistent-grid fused kernel with DIY grid barriers.
// Phase 1: 2 CTAs per batch row -> half-row histogram -> partial pooled halves.
// Phase 2: layer1 as tiled GEMM (32 cols x 4 rows per CTA, 8-way k-split).
// Phase 3: layer2 same, writes output.

__device__ unsigned g_bar[2];                 // zero-init; monotonic across launches
__device__ float g_pooled[BB][2][DD];         // pooled halves
__device__ float g_h[BB][DD];                 // layer1 output

__device__ __forceinline__ void grid_barrier(int idx, int tid) {
    __syncthreads();
    if (tid == 0) {
        __threadfence();
        unsigned ticket = atomicAdd(&g_bar[idx], 1u);
        unsigned target = ticket - (ticket % (unsigned)GRID) + (unsigned)GRID;
        while ((int)(*(volatile unsigned*)&g_bar[idx] - target) < 0) { }
        __threadfence();
    }
    __syncthreads();
}

__global__ __launch_bounds__(NT, 1) void palace_prot_net_persistent(
    const void* __restrict__ Xraw,       // [B, L] int32 or int64 (runtime detect)
    const void* __restrict__ VLraw,      // [B]    int32 or int64
    const float* __restrict__ emb,       // [33, 256]
    const float* __restrict__ W1,        // [256, 256]
    const float* __restrict__ b1,        // [256]
    const float* __restrict__ W2,        // [256, 256]
    const float* __restrict__ b2,        // [256]
    float* __restrict__ out)             // [B, 256]
{
    const int c   = blockIdx.x;
    const int tid = threadIdx.x;
    const int wid = tid >> 5;

    __shared__ int   whist[NW * VV];
    __shared__ float cntf[VV];
    __shared__ float pr[4][DD];     // staged activations (4 rows)
    __shared__ float part[32][32];  // k-partition partials

    // ---- dtype detection (int64 vs int32 token buffer) ----
    // Odd 32-bit words of row 0: all-zero => int64 (tokens < 33), else int32.
    const int* xi = (const int*)Xraw;
    int nz = xi[2 * tid + 1];
    const int is64 = (__syncthreads_or(nz) == 0);

    // ================= Phase 1: half-row histogram -> pooled half =========
    {
        const int r    = c >> 1;
        const int half = c & 1;

        long long vl;
        if (is64) vl = ((const long long*)VLraw)[r];
        else      vl = (long long)((const int*)VLraw)[r];

        for (int i = tid; i < NW * VV; i += NT) whist[i] = 0;
        __syncthreads();

        const size_t base = (size_t)r * LL;
        const int l0 = half * (LL / 2) + (tid << 1);   // 2 tokens per thread
        int t0, t1;
        if (is64) {
            int4 v = *(const int4*)(xi + 2 * (base + l0));
            t0 = v.x; t1 = v.z;
        } else {
            int2 v = *(const int2*)(xi + base + l0);
            t0 = v.x; t1 = v.y;
        }
        int* myh = &whist[wid * VV];
        if (l0 + 0 < vl) atomicAdd(&myh[t0], 1);
        if (l0 + 1 < vl) atomicAdd(&myh[t1], 1);
        __syncthreads();

        if (tid < VV) {
            int s = 0;
            #pragma unroll
            for (int w = 0; w < NW; w++) s += whist[w * VV + tid];
            cntf[tid] = (float)s;
        }
        __syncthreads();

        if (tid < DD) {
            float acc = 0.f;
            #pragma unroll
            for (int v = 0; v < VV; v++)
                acc = fmaf(cntf[v], emb[v * DD + tid], acc);
            g_pooled[r][half][tid] = acc;
        }
    }

    grid_barrier(0, tid);

    // Tile coords for both layer phases
    const int cg  = c & 7;          // column group: 32 cols
    const int rg4 = (c >> 3) * 4;   // row group: 4 rows
    const int lane = tid & 31;
    const int w    = tid >> 5;      // 0..31
    const int row  = w & 3;         // 0..3
    const int kp   = w >> 2;        // 0..7
    const int k0   = kp * 32;
    const int col  = cg * 32 + lane;

    // ================= Phase 2: layer1 ====================================
    {
        // stage pooled rows (sum the two halves; fixed order => deterministic)
        const int sr = tid >> 8;    // 0..3
        const int sk = tid & 255;
        pr[sr][sk] = __ldcg(&g_pooled[rg4 + sr][0][sk]) +
                     __ldcg(&g_pooled[rg4 + sr][1][sk]);
        __syncthreads();

        float a0 = 0.f, a1 = 0.f, a2 = 0.f, a3 = 0.f;
        const float* wp = W1 + (size_t)k0 * DD + col;
        #pragma unroll
        for (int i = 0; i < 32; i += 4) {
            a0 = fmaf(pr[row][k0 + i + 0], wp[(i + 0) * DD], a0);
            a1 = fmaf(pr[row][k0 + i + 1], wp[(i + 1) * DD], a1);
            a2 = fmaf(pr[row][k0 + i + 2], wp[(i + 2) * DD], a2);
            a3 = fmaf(pr[row][k0 + i + 3], wp[(i + 3) * DD], a3);
        }
        part[w][lane] = (a0 + a1) + (a2 + a3);
        __syncthreads();

        if (w < 4) {
            float s = b1[col];
            #pragma unroll
            for (int p = 0; p < 8; p++) s += part[p * 4 + w][lane];
            g_h[rg4 + w][col] = fmaxf(s, 0.f);
        }
    }

    grid_barrier(1, tid);

    // ================= Phase 3: layer2 ====================================
    {
        const int sr = tid >> 8;
        const int sk = tid & 255;
        pr[sr][sk] = __ldcg(&g_h[rg4 + sr][sk]);
        __syncthreads();

        float a0 = 0.f, a1 = 0.f, a2 = 0.f, a3 = 0.f;
        const float* wp = W2 + (size_t)k0 * DD + col;
        #pragma unroll
        for (int i = 0; i < 32; i += 4) {
            a0 = fmaf(pr[row][k0 + i + 0], wp[(i + 0) * DD], a0);
            a1 = fmaf(pr[row][k0 + i + 1], wp[(i + 1) * DD], a1);
            a2 = fmaf(pr[row][k0 + i + 2], wp[(i + 2) * DD], a2);
            a3 = fmaf(pr[row][k0 + i + 3], wp[(i + 3) * DD], a3);
        }
        part[w][lane] = (a0 + a1) + (a2 + a3);
        __syncthreads();

        if (w < 4) {
            float s = b2[col];
            #pragma unroll
            for (int p = 0; p < 8; p++) s += part[p * 4 + w][lane];
            out[(rg4 + w) * DD + col] = fmaxf(s, 0.f);
        }
    }
}

extern "C" void kernel_launch(void* const* d_in, const int* in_sizes, int n_in,
                              void* d_out, int out_size) {
    // metadata order: X, valid_lens, emb, W1, b1, W2, b2
    const void*  X   = d_in[0];
    const void*  VL  = d_in[1];
    const float* emb = (const float*)d_in[2];
    const float* W1  = (const float*)d_in[3];
    const float* b1  = (const float*)d_in[4];
    const float* W2  = (const float*)d_in[5];
    const float* b2  = (const float*)d_in[6];
    float* out = (float*)d_out;

    palace_prot_net_persistent<<<GRID, NT>>>(X, VL, emb, W1, b1, W2, b2, out);
}

// round 6
// speedup vs baseline: 1.0330x; 1.0330x over previous
#include <cuda_runtime.h>
#include <cuda_bf16.h>

#define BB   64
#define LL   4096
#define DD   256
#define VV   33
#define NT   1024
#define NW   (NT / 32)

// Scratch (device globals; no allocation)
__device__ float g_cnt[BB][VV];     // per-row token counts (masked)
__device__ float g_M1[VV][DD];      // M1 = emb @ W1  (33 x 256)

// ============================ Kernel 1 =====================================
// CTAs 0..63  : histogram of row b over valid prefix -> g_cnt[b][*]
// CTAs 64..96 : one row v of M1 = emb @ W1 (K=256, 4-way k-split)
__global__ __launch_bounds__(NT, 1) void k1_hist_m1(
    const void* __restrict__ Xraw,       // [B, L] int32 or int64 (runtime detect)
    const void* __restrict__ VLraw,      // [B]    int32 or int64
    const float* __restrict__ emb,       // [33, 256]
    const float* __restrict__ W1)        // [256, 256]
{
    const int c   = blockIdx.x;
    const int tid = threadIdx.x;

    if (c < BB) {
        // ---------------- histogram for row c ----------------
        __shared__ int whist[NW * VV];
        const int wid = tid >> 5;

        // dtype detection: odd 32-bit words of row 0's first 1024 tokens.
        // int64 tokens (<33) => all high words zero; int32 => random tokens
        // in [0,33) => some odd word nonzero w.h.p. (P(miss) ~ 33^-1024).
        const int* xi = (const int*)Xraw;
        int nz = xi[2 * tid + 1];
        const int is64 = (__syncthreads_or(nz) == 0);

        long long vl;
        if (is64) vl = ((const long long*)VLraw)[c];
        else      vl = (long long)((const int*)VLraw)[c];

        for (int i = tid; i < NW * VV; i += NT) whist[i] = 0;
        __syncthreads();

        const size_t base = (size_t)c * LL;
        const int l0 = tid << 2;                 // 4 tokens per thread
        int t0, t1, t2, t3;
        if (is64) {
            const int4* p = (const int4*)(xi + 2 * (base + l0));
            int4 v0 = p[0], v1 = p[1];
            t0 = v0.x; t1 = v0.z; t2 = v1.x; t3 = v1.z;
        } else {
            int4 v = *(const int4*)(xi + base + l0);
            t0 = v.x; t1 = v.y; t2 = v.z; t3 = v.w;
        }
        int* myh = &whist[wid * VV];
        if (l0 + 0 < vl) atomicAdd(&myh[t0], 1);
        if (l0 + 1 < vl) atomicAdd(&myh[t1], 1);
        if (l0 + 2 < vl) atomicAdd(&myh[t2], 1);
        if (l0 + 3 < vl) atomicAdd(&myh[t3], 1);
        __syncthreads();

        if (tid < VV) {
            int s = 0;
            #pragma unroll
            for (int w = 0; w < NW; w++) s += whist[w * VV + tid];
            g_cnt[c][tid] = (float)s;
        }
    } else {
        // ---------------- M1 row v = emb[v] @ W1 ----------------
        const int v = c - BB;                    // 0..32
        __shared__ float erow[DD];
        __shared__ float part[3][DD];

        if (tid < DD) erow[tid] = emb[v * DD + tid];
        __syncthreads();

        const int j  = tid & (DD - 1);
        const int kp = tid >> 8;                 // 0..3
        const int k0 = kp << 6;

        float a0 = 0.f, a1 = 0.f, a2 = 0.f, a3 = 0.f;
        const float* wp = W1 + (size_t)k0 * DD + j;
        #pragma unroll 16
        for (int i = 0; i < 64; i += 4) {
            a0 = fmaf(erow[k0 + i + 0], wp[(i + 0) * DD], a0);
            a1 = fmaf(erow[k0 + i + 1], wp[(i + 1) * DD], a1);
            a2 = fmaf(erow[k0 + i + 2], wp[(i + 2) * DD], a2);
            a3 = fmaf(erow[k0 + i + 3], wp[(i + 3) * DD], a3);
        }
        float acc = (a0 + a1) + (a2 + a3);
        if (kp) part[kp - 1][j] = acc;
        __syncthreads();
        if (kp == 0)
            g_M1[v][j] = acc + part[0][j] + part[1][j] + part[2][j];
    }
}

// ============================ Kernel 2 =====================================
// One CTA per batch row: h = relu(cnt @ M1 + b1)  (K=33),
// then out = relu(h @ W2 + b2) with 4-way k-split.
__global__ __launch_bounds__(NT, 1) void k2_mlp(
    const float* __restrict__ b1,
    const float* __restrict__ W2,
    const float* __restrict__ b2,
    float* __restrict__ out)
{
    const int b   = blockIdx.x;
    const int tid = threadIdx.x;

    __shared__ float cnt[VV];
    __shared__ float hbuf[DD];
    __shared__ float part[3][DD];

    if (tid < VV) cnt[tid] = __ldcg(&g_cnt[b][tid]);
    __syncthreads();

    const int j  = tid & (DD - 1);
    const int kp = tid >> 8;
    const int k0 = kp << 6;

    // ---- layer 1: K = 33 only (256 threads suffice) ----
    if (kp == 0) {
        float a0 = 0.f, a1 = 0.f, a2 = 0.f;
        #pragma unroll
        for (int v = 0; v < 33; v += 3) {
            a0 = fmaf(cnt[v + 0], __ldcg(&g_M1[v + 0][j]), a0);
            if (v + 1 < VV) a1 = fmaf(cnt[v + 1], __ldcg(&g_M1[v + 1][j]), a1);
            if (v + 2 < VV) a2 = fmaf(cnt[v + 2], __ldcg(&g_M1[v + 2][j]), a2);
        }
        hbuf[j] = fmaxf(a0 + a1 + a2 + b1[j], 0.f);
    }
    __syncthreads();

    // ---- layer 2: K = 256, 4-way k-split ----
    {
        float a0 = 0.f, a1 = 0.f, a2 = 0.f, a3 = 0.f;
        const float* wp = W2 + (size_t)k0 * DD + j;
        #pragma unroll 16
        for (int i = 0; i < 64; i += 4) {
            a0 = fmaf(hbuf[k0 + i + 0], wp[(i + 0) * DD], a0);
            a1 = fmaf(hbuf[k0 + i + 1], wp[(i + 1) * DD], a1);
            a2 = fmaf(hbuf[k0 + i + 2], wp[(i + 2) * DD], a2);
            a3 = fmaf(hbuf[k0 + i + 3], wp[(i + 3) * DD], a3);
        }
        float acc = (a0 + a1) + (a2 + a3);
        if (kp) part[kp - 1][j] = acc;
        __syncthreads();
        if (kp == 0) {
            acc += part[0][j] + part[1][j] + part[2][j];
            out[b * DD + j] = fmaxf(acc + b2[j], 0.f);
        }
    }
}

extern "C" void kernel_launch(void* const* d_in, const int* in_sizes, int n_in,
                              void* d_out, int out_size) {
    // metadata order: X, valid_lens, emb, W1, b1, W2, b2
    const void*  X   = d_in[0];
    const void*  VL  = d_in[1];
    const float* emb = (const float*)d_in[2];
    const float* W1  = (const float*)d_in[3];
    const float* b1  = (const float*)d_in[4];
    const float* W2  = (const float*)d_in[5];
    const float* b2  = (const float*)d_in[6];
    float* out = (float*)d_out;

    k1_hist_m1<<<BB + VV, NT>>>(X, VL, emb, W1);
    k2_mlp<<<BB, NT>>>(b1, W2, b2, out);
}

// round 7
// speedup vs baseline: 1.1629x; 1.1257x over previous
#include <cuda_runtime.h>
#include <cuda_bf16.h>

#define BB   64
#define LL   4096
#define DD   256
#define VV   33
#define NT   512
#define NWH  (NT / 32)          // warps per hist CTA

#define HIST_CTAS 128           // 2 per batch row
#define M1_CTAS   66            // 2 per M1 row (33 rows x half-cols)

// Scratch (device globals; no allocation, fully overwritten every launch)
__device__ float g_cnt2[BB][2][VV];   // per-row half-histograms
__device__ float g_M1[VV][DD];        // M1 = emb @ W1  (33 x 256)

// ============================ Kernel 1 =====================================
// CTAs 0..127   : half-row histogram (match_any-aggregated smem atomics)
// CTAs 128..193 : half-row of M1 = emb @ W1 (128 cols, 4-way k-split K=64)
__global__ __launch_bounds__(NT, 2) void k1_hist_m1(
    const void* __restrict__ Xraw,       // [B, L] int32 or int64 (runtime detect)
    const void* __restrict__ VLraw,      // [B]    int32 or int64
    const float* __restrict__ emb,       // [33, 256]
    const float* __restrict__ W1)        // [256, 256]
{
    const int c   = blockIdx.x;
    const int tid = threadIdx.x;

    if (c < HIST_CTAS) {
        // ---------------- histogram: row r, half h (2048 tokens) ----------
        __shared__ int whist[NWH * VV];
        const int r    = c >> 1;
        const int half = c & 1;
        const int wid  = tid >> 5;
        const int lane = tid & 31;

        // dtype detection: odd 32-bit words of row 0's first 512 tokens.
        // int64 tokens (<33) => high words all zero; int32 => some odd word
        // is a nonzero random token w.h.p. (P(miss) ~ 33^-512).
        const int* xi = (const int*)Xraw;
        int nz = xi[2 * tid + 1];
        const int is64 = (__syncthreads_or(nz) == 0);

        long long vl;
        if (is64) vl = ((const long long*)VLraw)[r];
        else      vl = (long long)((const int*)VLraw)[r];

        for (int i = tid; i < NWH * VV; i += NT) whist[i] = 0;
        __syncthreads();

        const size_t base = (size_t)r * LL;
        const int l0 = half * (LL / 2) + (tid << 2);   // 4 tokens per thread
        int t[4];
        if (is64) {
            const int4* p = (const int4*)(xi + 2 * (base + l0));
            int4 v0 = p[0], v1 = p[1];
            t[0] = v0.x; t[1] = v0.z; t[2] = v1.x; t[3] = v1.z;
        } else {
            int4 v = *(const int4*)(xi + base + l0);
            t[0] = v.x; t[1] = v.y; t[2] = v.z; t[3] = v.w;
        }
        int* myh = &whist[wid * VV];
        #pragma unroll
        for (int k = 0; k < 4; k++) {
            int tok = (l0 + k < vl) ? t[k] : 64;       // 64 = masked sentinel
            unsigned m = __match_any_sync(0xffffffffu, tok);
            int leader = __ffs(m) - 1;
            if (lane == leader && tok < VV)
                atomicAdd(&myh[tok], __popc(m));
        }
        __syncthreads();

        if (tid < VV) {
            int s = 0;
            #pragma unroll
            for (int w = 0; w < NWH; w++) s += whist[w * VV + tid];
            g_cnt2[r][half][tid] = (float)s;
        }
    } else {
        // ---------------- M1[v][half cols] = emb[v] @ W1 -------------------
        const int idx  = c - HIST_CTAS;              // 0..65
        const int v    = idx >> 1;                   // 0..32
        const int half = idx & 1;
        __shared__ float erow[DD];
        __shared__ float part[3][128];

        if (tid < DD) erow[tid] = emb[v * DD + tid];
        __syncthreads();

        const int jl  = tid & 127;
        const int col = half * 128 + jl;
        const int kp  = tid >> 7;                    // 0..3
        const int k0  = kp << 6;                     // K=64 per partition

        float a0 = 0.f, a1 = 0.f, a2 = 0.f, a3 = 0.f;
        const float* wp = W1 + (size_t)k0 * DD + col;
        #pragma unroll 16
        for (int i = 0; i < 64; i += 4) {
            a0 = fmaf(erow[k0 + i + 0], wp[(i + 0) * DD], a0);
            a1 = fmaf(erow[k0 + i + 1], wp[(i + 1) * DD], a1);
            a2 = fmaf(erow[k0 + i + 2], wp[(i + 2) * DD], a2);
            a3 = fmaf(erow[k0 + i + 3], wp[(i + 3) * DD], a3);
        }
        float acc = (a0 + a1) + (a2 + a3);
        if (kp) part[kp - 1][jl] = acc;
        __syncthreads();
        if (kp == 0)
            g_M1[v][col] = acc + part[0][jl] + part[1][jl] + part[2][jl];
    }
}

// ============================ Kernel 2 =====================================
// 128 CTAs: (row b, column-half). layer1 (K=33) duplicated per CTA,
// layer2 on 128 cols with 4-way k-split (K=64 chains).
__global__ __launch_bounds__(NT, 2) void k2_mlp(
    const float* __restrict__ b1,
    const float* __restrict__ W2,
    const float* __restrict__ b2,
    float* __restrict__ out)
{
    const int c   = blockIdx.x;
    const int tid = threadIdx.x;
    const int b    = c >> 1;
    const int half = c & 1;

    __shared__ float cnt[VV];
    __shared__ float hbuf[DD];
    __shared__ float part[3][128];

    if (tid < VV)
        cnt[tid] = __ldcg(&g_cnt2[b][0][tid]) + __ldcg(&g_cnt2[b][1][tid]);
    __syncthreads();

    // ---- layer 1: full 256-wide h, K = 33 ----
    if (tid < DD) {
        const int j = tid;
        float a0 = 0.f, a1 = 0.f, a2 = 0.f;
        #pragma unroll
        for (int v = 0; v < 33; v += 3) {
            a0 = fmaf(cnt[v + 0], __ldcg(&g_M1[v + 0][j]), a0);
            if (v + 1 < VV) a1 = fmaf(cnt[v + 1], __ldcg(&g_M1[v + 1][j]), a1);
            if (v + 2 < VV) a2 = fmaf(cnt[v + 2], __ldcg(&g_M1[v + 2][j]), a2);
        }
        hbuf[j] = fmaxf(a0 + a1 + a2 + b1[j], 0.f);
    }
    __syncthreads();

    // ---- layer 2: 128 cols, 4-way k-split (K=64 per thread) ----
    {
        const int jl  = tid & 127;
        const int col = half * 128 + jl;
        const int kp  = tid >> 7;
        const int k0  = kp << 6;

        float a0 = 0.f, a1 = 0.f, a2 = 0.f, a3 = 0.f;
        const float* wp = W2 + (size_t)k0 * DD + col;
        #pragma unroll 16
        for (int i = 0; i < 64; i += 4) {
            a0 = fmaf(hbuf[k0 + i + 0], wp[(i + 0) * DD], a0);
            a1 = fmaf(hbuf[k0 + i + 1], wp[(i + 1) * DD], a1);
            a2 = fmaf(hbuf[k0 + i + 2], wp[(i + 2) * DD], a2);
            a3 = fmaf(hbuf[k0 + i + 3], wp[(i + 3) * DD], a3);
        }
        float acc = (a0 + a1) + (a2 + a3);
        if (kp) part[kp - 1][jl] = acc;
        __syncthreads();
        if (kp == 0) {
            acc += part[0][jl] + part[1][jl] + part[2][jl];
            out[b * DD + col] = fmaxf(acc + b2[col], 0.f);
        }
    }
}

extern "C" void kernel_launch(void* const* d_in, const int* in_sizes, int n_in,
                              void* d_out, int out_size) {
    // metadata order: X, valid_lens, emb, W1, b1, W2, b2
    const void*  X   = d_in[0];
    const void*  VL  = d_in[1];
    const float* emb = (const float*)d_in[2];
    const float* W1  = (const float*)d_in[3];
    const float* b1  = (const float*)d_in[4];
    const float* W2  = (const float*)d_in[5];
    const float* b2  = (const float*)d_in[6];
    float* out = (float*)d_out;

    k1_hist_m1<<<HIST_CTAS + M1_CTAS, NT>>>(X, VL, emb, W1);
    k2_mlp<<<128, NT>>>(b1, W2, b2, out);
}